// round 2
// baseline (speedup 1.0000x reference)
#include <cuda_runtime.h>

// NPZD Euler integration: 1024*52 independent chains of 168 steps.
// t_idx[w,j] = 168*w + j exactly -> f/delta are contiguous 168-float windows.
// Round-2 changes vs round-1 (43us):
//  * CHUNK=24: output sample falls at compile-time jj==23, once per chunk,
//    sample index = c+1 -> no per-step branch/predicate machinery.
//  * 2 chains per thread (w and w+26, same batch b -> shared params) for 2x ILP
//    against the ~65-cycle serial RCP/EX2/FMA recurrence.
//  * TPB=64 keeps 416 blocks -> same balanced single wave (2-3 blocks/SM).

#define BB 1024
#define WW 52
#define HOURS 8760
#define TSTEPS 168
#define TPB 64
#define CHUNK 24
#define NCHUNK 7               // 7 * 24 = 168
#define PITCH 25               // odd -> conflict-free LDS (gcd(25,32)=1)
#define ROWS (2 * TPB)         // 128 chains per block

__global__ __launch_bounds__(TPB) void npzd_kernel(
    const float* __restrict__ X_in,      // (B, W, 5, 1)
    const float* __restrict__ gf,        // (B, HOURS)
    const float* __restrict__ gd,        // (B, HOURS)
    const float* __restrict__ params,    // (B, 10)
    float* __restrict__ out)             // (B, W, 4, 8)
{
    __shared__ float fsm[ROWS * PITCH];
    __shared__ float dsm[ROWS * PITCH];
    __shared__ int   bases[ROWS];

    const int t  = threadIdx.x;
    const int p2 = blockIdx.x * TPB + t;     // 0 .. 26623
    const int b  = p2 / 26;
    const int w  = p2 - b * 26;              // chain A = (b,w), chain B = (b,w+26)

    const int pA = b * WW + w;
    const int pB = pA + 26;

    bases[t]       = b * HOURS + w * TSTEPS;
    bases[TPB + t] = b * HOURS + (w + 26) * TSTEPS;

    const float dt  = 1.0f / 24.0f;
    const float thr = 0.01f;

    const float* pp = params + b * 10;
    const float Kn    = pp[0] * 1.0f;
    const float Rm    = pp[1] * 2.0f;
    const float gz    = pp[2] * 0.1f;
    const float lam   = pp[3] * 0.05f;
    const float eps   = pp[4] * 0.1f;
    const float alpha = pp[5] * 0.3f;
    const float beta  = pp[6] * 0.6f;
    const float rr    = pp[7] * 0.15f;
    const float phi   = pp[8] * 0.4f;
    const float Sw    = pp[9] * 0.1f;

    // fold dt into coefficients once (shared by both chains)
    const float dta   = dt * alpha;
    const float dte   = dt * eps;
    const float dtg   = dt * gz;
    const float dtphi = dt * phi;
    const float dtb   = dt * beta;
    const float dtr   = dt * rr;
    const float dtab  = dt * (1.0f - alpha - beta);
    const float cp    = dt * (eps + rr);
    const float cd    = dt * (phi + Sw);

    // initial states
    const float* xA = X_in + (size_t)pA * 5;
    const float* xB = X_in + (size_t)pB * 5;
    float NA = xA[1], PA = xA[2], ZA = xA[3], DA = xA[4];
    float NB = xB[1], PB = xB[2], ZB = xB[3], DB = xB[4];

    float* oA = out + (size_t)pA * 32;       // [4 states][8 samples]
    float* oB = out + (size_t)pB * 32;
    oA[0] = NA; oA[8]  = PA; oA[16] = ZA; oA[24] = DA;
    oB[0] = NB; oB[8]  = PB; oB[16] = ZB; oB[24] = DB;

    float gamA = __fdividef(NA, Kn + NA);
    float zooA = Rm * (1.0f - __expf(-lam * fmaxf(thr, PA))) * fmaxf(thr, ZA);
    float gamB = __fdividef(NB, Kn + NB);
    float zooB = Rm * (1.0f - __expf(-lam * fmaxf(thr, PB))) * fmaxf(thr, ZB);

    auto step = [&](float ft, float dl,
                    float& N, float& P, float& Z, float& D,
                    float& gam, float& zoo)
    {
        const float mP = fmaxf(thr, P);
        const float up = gam * ft * mP;          // Vm = 1
        const float dd = dt * dl;

        float N1 = fmaf(-dt,   up,  N);
        N1 = fmaf(dta,   zoo,      N1);
        N1 = fmaf(dte,   P,        N1);
        N1 = fmaf(dtg,   Z,        N1);
        N1 = fmaf(dtphi, D,        N1);
        N1 = fmaf(dd,    8.0f - N, N1);          // Q0 = 8

        float P1 = fmaf(dt, up, P);
        P1 = fmaf(-dt, zoo, P1);
        P1 = fmaf(-cp, P,   P1);
        P1 = fmaf(-dd, P,   P1);

        float Z1 = fmaf(dtb,  zoo, Z);
        Z1 = fmaf(-dtg, Z, Z1);
        Z1 = fmaf(-dd,  Z, Z1);

        float D1 = fmaf(dtr,  P,   D);
        D1 = fmaf(dtab, zoo, D1);
        D1 = fmaf(-cd,  D,   D1);
        D1 = fmaf(-dd,  D,   D1);

        N = N1; P = P1; Z = Z1; D = D1;

        gam = __fdividef(N1, Kn + N1);
        const float ex = __expf(-lam * fmaxf(thr, P1));
        zoo = Rm * (1.0f - ex) * fmaxf(thr, Z1);
    };

    const int fbA = t * PITCH;
    const int fbB = (TPB + t) * PITCH;

    #pragma unroll 1
    for (int c = 0; c < NCHUNK; ++c) {
        __syncthreads();   // also covers bases[] visibility on c==0
        // cooperative chunk load: 128 rows x 24 floats, float4-granular.
        // bases are multiples of 8 floats (w*168 + b*8760) -> 32B-aligned,
        // chunk offsets 24c also multiples of 8 -> float4 safe.
        const int cbase = c * CHUNK;
        #pragma unroll
        for (int r = 0; r < 12; ++r) {
            int i   = r * TPB + t;               // 0 .. 767
            int row = i / 6;                     // 6 float4 per row
            int e   = i - row * 6;
            int g   = bases[row] + cbase + e * 4;
            float4 fv = *reinterpret_cast<const float4*>(gf + g);
            float4 dv = *reinterpret_cast<const float4*>(gd + g);
            int so = row * PITCH + e * 4;        // pitch odd -> scalar stores
            fsm[so + 0] = fv.x; fsm[so + 1] = fv.y;
            fsm[so + 2] = fv.z; fsm[so + 3] = fv.w;
            dsm[so + 0] = dv.x; dsm[so + 1] = dv.y;
            dsm[so + 2] = dv.z; dsm[so + 3] = dv.w;
        }
        __syncthreads();

        #pragma unroll
        for (int jj = 0; jj < CHUNK; ++jj) {
            step(fsm[fbA + jj], dsm[fbA + jj], NA, PA, ZA, DA, gamA, zooA);
            step(fsm[fbB + jj], dsm[fbB + jj], NB, PB, ZB, DB, gamB, zooB);
        }

        // exactly one output sample per 24-step chunk, compile-time position
        const int k = c + 1;
        oA[k] = NA; oA[8 + k] = PA; oA[16 + k] = ZA; oA[24 + k] = DA;
        oB[k] = NB; oB[8 + k] = PB; oB[16 + k] = ZB; oB[24 + k] = DB;
    }
}

extern "C" void kernel_launch(void* const* d_in, const int* in_sizes, int n_in,
                              void* d_out, int out_size) {
    const float* X_in  = (const float*)d_in[0];
    const float* gf    = (const float*)d_in[1];
    const float* gd    = (const float*)d_in[2];
    const float* par   = (const float*)d_in[3];
    float* out = (float*)d_out;

    npzd_kernel<<<(BB * WW / 2) / TPB, TPB>>>(X_in, gf, gd, par, out);
}

// round 3
// speedup vs baseline: 1.4625x; 1.4625x over previous
#include <cuda_runtime.h>

// NPZD Euler: 1024*52 independent 168-step chains.
// t_idx[w,j] = 168*w + j exactly -> f/delta are contiguous 168-float windows.
//
// Round-3 (best so far R1 = 43us; R2 regression showed warp count dominates):
//  * back to 1 chain/thread, TPB=128, 416 blocks (max 1664 warps).
//  * CHUNK=24: sample store at compile-time jj boundary -> branchless hot loop.
//  * (f,d) interleaved float2 SMEM, pitch 25 f2 -> one conflict-free LDS.64/step.
//  * tree-shaped update math + raw ex2/rcp.approx -> ~48-cycle loop-carried path.

#define BB 1024
#define WW 52
#define HOURS 8760
#define TSTEPS 168
#define TPB 128
#define CHUNK 24
#define NCHUNK 7               // 7 * 24 = 168
#define PITCH 25               // float2 units; 50-word stride -> conflict-free

__device__ __forceinline__ float ex2_approx(float x) {
    float r;
    asm("ex2.approx.f32 %0, %1;" : "=f"(r) : "f"(x));
    return r;
}
__device__ __forceinline__ float rcp_approx(float x) {
    float r;
    asm("rcp.approx.f32 %0, %1;" : "=f"(r) : "f"(x));
    return r;
}

__global__ __launch_bounds__(TPB) void npzd_kernel(
    const float* __restrict__ X_in,      // (B, W, 5, 1)
    const float* __restrict__ gf,        // (B, HOURS)
    const float* __restrict__ gd,        // (B, HOURS)
    const float* __restrict__ params,    // (B, 10)
    float* __restrict__ out)             // (B, W, 4, 8)
{
    __shared__ float2 ism[TPB * PITCH];  // interleaved (f, delta)
    __shared__ int    bases[TPB];

    const int t = threadIdx.x;
    const int p = blockIdx.x * TPB + t;  // pair index
    const int b = p / WW;
    const int w = p - b * WW;

    bases[t] = b * HOURS + w * TSTEPS;   // multiple of 8 -> float4-aligned

    const float dt  = 1.0f / 24.0f;
    const float thr = 0.01f;

    const float* pp = params + b * 10;
    const float Kn    = pp[0] * 1.0f;
    const float Rm    = pp[1] * 2.0f;
    const float gz    = pp[2] * 0.1f;
    const float lam   = pp[3] * 0.05f;
    const float eps   = pp[4] * 0.1f;
    const float alpha = pp[5] * 0.3f;
    const float beta  = pp[6] * 0.6f;
    const float rr    = pp[7] * 0.15f;
    const float phi   = pp[8] * 0.4f;
    const float Sw    = pp[9] * 0.1f;

    const float dta   = dt * alpha;
    const float dte   = dt * eps;
    const float dtg   = dt * gz;
    const float dtphi = dt * phi;
    const float dtb   = dt * beta;
    const float dtr   = dt * rr;
    const float dtab  = dt * (1.0f - alpha - beta);
    const float cp    = dt * (eps + rr);       // (eps + r)*dt
    const float cd    = dt * (phi + Sw);       // (phi + Sw)*dt
    const float nl    = -lam * 1.44269504f;    // fold log2(e) into lambda

    const float* xi = X_in + (size_t)p * 5;
    float N = xi[1];
    float P = xi[2];
    float Z = xi[3];
    float D = xi[4];

    float* op = out + (size_t)p * 32;          // [4 states][8 samples]
    op[0]  = N;
    op[8]  = P;
    op[16] = Z;
    op[24] = D;

    float gam = N * rcp_approx(Kn + N);
    float mP  = fmaxf(thr, P);
    float zoo;
    {
        float RmZ = Rm * fmaxf(thr, Z);
        float ex  = ex2_approx(nl * mP);
        zoo = fmaf(-RmZ, ex, RmZ);
    }

    const int fb = t * PITCH;

    #pragma unroll 1
    for (int c = 0; c < NCHUNK; ++c) {
        __syncthreads();   // protects ism reuse; covers bases[] on c==0
        // cooperative chunk load: 128 rows x 24 floats per array, float4 LDG,
        // interleaved float2 STS. bases + 24c are multiples of 8 -> aligned.
        const int cbase = c * CHUNK;
        #pragma unroll
        for (int r = 0; r < 6; ++r) {
            int i   = r * TPB + t;             // 0 .. 767
            int row = i / 6;                   // 6 float4 per row
            int e   = i - row * 6;
            int g   = bases[row] + cbase + e * 4;
            float4 fv = *reinterpret_cast<const float4*>(gf + g);
            float4 dv = *reinterpret_cast<const float4*>(gd + g);
            int so = row * PITCH + e * 4;
            ism[so + 0] = make_float2(fv.x, dv.x);
            ism[so + 1] = make_float2(fv.y, dv.y);
            ism[so + 2] = make_float2(fv.z, dv.z);
            ism[so + 3] = make_float2(fv.w, dv.w);
        }
        __syncthreads();

        #pragma unroll
        for (int jj = 0; jj < CHUNK; ++jj) {
            const float2 fd = ism[fb + jj];
            const float ft = fd.x;
            const float dd = dt * fd.y;

            // off-critical-path combos
            const float cpd = cp  + dd;
            const float gdd = dtg + dd;
            const float cdd = cd  + dd;

            const float up   = (gam * ft) * mP;      // Vm = 1
            const float dtup = dt * up;

            // N1 = N(1-dd) + (dta*zoo + dte*P) + (dtg*Z + dtphi*D) + (8dd - dt*up)
            const float t1 = fmaf(dta, zoo, dte * P);
            const float t2 = fmaf(dtg, Z, dtphi * D);
            const float t3 = fmaf(8.0f, dd, -dtup);  // Q0 = 8
            const float t4 = fmaf(-dd, N, N);
            const float N1 = (t1 + t2) + (t3 + t4);

            // P1 = P(1 - cp - dd) + dt*up - dt*zoo
            const float q1 = fmaf(-cpd, P, P);
            const float q2 = fmaf(-dt, zoo, dtup);
            const float P1 = q1 + q2;

            // Z1 = Z(1 - dtg - dd) + dtb*zoo
            const float Z1 = fmaf(dtb, zoo, fmaf(-gdd, Z, Z));

            // D1 = D(1 - cd - dd) + dtr*P + dtab*zoo
            const float u1 = fmaf(-cdd, D, D);
            const float u2 = fmaf(dtr, P, dtab * zoo);
            const float D1 = u1 + u2;

            N = N1; P = P1; Z = Z1; D = D1;

            gam = N1 * rcp_approx(Kn + N1);
            mP  = fmaxf(thr, P1);
            const float RmZ = Rm * fmaxf(thr, Z1);
            const float ex  = ex2_approx(nl * mP);
            zoo = fmaf(-RmZ, ex, RmZ);
        }

        // exactly one output sample per 24-step chunk, compile-time position
        const int k = c + 1;
        op[k]      = N;
        op[8 + k]  = P;
        op[16 + k] = Z;
        op[24 + k] = D;
    }
}

extern "C" void kernel_launch(void* const* d_in, const int* in_sizes, int n_in,
                              void* d_out, int out_size) {
    const float* X_in  = (const float*)d_in[0];
    const float* gf    = (const float*)d_in[1];
    const float* gd    = (const float*)d_in[2];
    const float* par   = (const float*)d_in[3];
    float* out = (float*)d_out;

    npzd_kernel<<<(BB * WW) / TPB, TPB>>>(X_in, gf, gd, par, out);
}

// round 6
// speedup vs baseline: 1.6315x; 1.1156x over previous
#include <cuda_runtime.h>

// NPZD Euler: 1024*52 independent 168-step chains.
// t_idx[w,j] = 168*w + j exactly -> f/delta are contiguous 168-float windows.
//
// Round-6 = Round-4/5 resubmitted (both benches died to the same container
// bring-up infra failure also seen in Round 0 with the bare stub).
// Changes vs best-passing R3 (39.2us):
//  * register-staged prefetch: chunk c+1's 12x LDG.128 issued right after the
//    post-STS barrier, consumed (STS) only after end-of-chunk barrier ->
//    DRAM latency fully hidden under the 24-step compute.
//  * __launch_bounds__(128, 3): reg ceiling 64 -> ~170, lets ptxas overlap
//    adjacent steps across the MUFU waits (occ is chain-capped anyway).
//  * dt*delta folded into the STS phase: SMEM holds (f, dt*delta).
//  * keeps: 1 chain/thread, 416x128 single wave, CHUNK=24 branchless sampling,
//    pitch-25 float2 conflict-free SMEM, tree-shaped update, raw ex2/rcp.

#define BB 1024
#define WW 52
#define HOURS 8760
#define TSTEPS 168
#define TPB 128
#define CHUNK 24
#define NCHUNK 7               // 7 * 24 = 168
#define PITCH 25               // float2 units; 50-word stride -> conflict-free

__device__ __forceinline__ float ex2_approx(float x) {
    float r;
    asm("ex2.approx.f32 %0, %1;" : "=f"(r) : "f"(x));
    return r;
}
__device__ __forceinline__ float rcp_approx(float x) {
    float r;
    asm("rcp.approx.f32 %0, %1;" : "=f"(r) : "f"(x));
    return r;
}

__global__ __launch_bounds__(TPB, 3) void npzd_kernel(
    const float* __restrict__ X_in,      // (B, W, 5, 1)
    const float* __restrict__ gf,        // (B, HOURS)
    const float* __restrict__ gd,        // (B, HOURS)
    const float* __restrict__ params,    // (B, 10)
    float* __restrict__ out)             // (B, W, 4, 8)
{
    __shared__ float2 ism[TPB * PITCH];  // interleaved (f, dt*delta)
    __shared__ int    bases[TPB];

    const int t = threadIdx.x;
    const int p = blockIdx.x * TPB + t;  // pair index
    const int b = p / WW;
    const int w = p - b * WW;

    bases[t] = b * HOURS + w * TSTEPS;   // multiple of 8 -> float4-aligned

    const float dt  = 1.0f / 24.0f;
    const float thr = 0.01f;

    const float* pp = params + b * 10;
    const float Kn    = pp[0] * 1.0f;
    const float Rm    = pp[1] * 2.0f;
    const float gz    = pp[2] * 0.1f;
    const float lam   = pp[3] * 0.05f;
    const float eps   = pp[4] * 0.1f;
    const float alpha = pp[5] * 0.3f;
    const float beta  = pp[6] * 0.6f;
    const float rr    = pp[7] * 0.15f;
    const float phi   = pp[8] * 0.4f;
    const float Sw    = pp[9] * 0.1f;

    const float dta   = dt * alpha;
    const float dte   = dt * eps;
    const float dtg   = dt * gz;
    const float dtphi = dt * phi;
    const float dtb   = dt * beta;
    const float dtr   = dt * rr;
    const float dtab  = dt * (1.0f - alpha - beta);
    const float cp    = dt * (eps + rr);       // (eps + r)*dt
    const float cd    = dt * (phi + Sw);       // (phi + Sw)*dt
    const float nl    = -lam * 1.44269504f;    // fold log2(e) into lambda

    const float* xi = X_in + (size_t)p * 5;
    float N = xi[1];
    float P = xi[2];
    float Z = xi[3];
    float D = xi[4];

    float* op = out + (size_t)p * 32;          // [4 states][8 samples]
    op[0]  = N;
    op[8]  = P;
    op[16] = Z;
    op[24] = D;

    float gam = N * rcp_approx(Kn + N);
    float mP  = fmaxf(thr, P);
    float zoo;
    {
        float RmZ = Rm * fmaxf(thr, Z);
        float ex  = ex2_approx(nl * mP);
        zoo = fmaf(-RmZ, ex, RmZ);
    }

    const int fb = t * PITCH;

    __syncthreads();                           // bases[] visible

    // register staging for the next chunk (cooperative slice, 48 floats)
    float4 fr[6], dr[6];

    // prefetch chunk 0
    #pragma unroll
    for (int r = 0; r < 6; ++r) {
        int i   = r * TPB + t;                 // 0 .. 767
        int row = i / 6;                       // 6 float4 per row
        int e   = i - row * 6;
        int g   = bases[row] + e * 4;
        fr[r] = *reinterpret_cast<const float4*>(gf + g);
        dr[r] = *reinterpret_cast<const float4*>(gd + g);
    }

    #pragma unroll 1
    for (int c = 0; c < NCHUNK; ++c) {
        // STS staged registers -> SMEM, folding dt into delta
        #pragma unroll
        for (int r = 0; r < 6; ++r) {
            int i   = r * TPB + t;
            int row = i / 6;
            int e   = i - row * 6;
            int so  = row * PITCH + e * 4;
            ism[so + 0] = make_float2(fr[r].x, dt * dr[r].x);
            ism[so + 1] = make_float2(fr[r].y, dt * dr[r].y);
            ism[so + 2] = make_float2(fr[r].z, dt * dr[r].z);
            ism[so + 3] = make_float2(fr[r].w, dt * dr[r].w);
        }
        __syncthreads();                       // chunk c ready in SMEM

        // prefetch chunk c+1 while computing chunk c (DRAM latency hidden)
        if (c < NCHUNK - 1) {
            const int cbase = (c + 1) * CHUNK;
            #pragma unroll
            for (int r = 0; r < 6; ++r) {
                int i   = r * TPB + t;
                int row = i / 6;
                int e   = i - row * 6;
                int g   = bases[row] + cbase + e * 4;
                fr[r] = *reinterpret_cast<const float4*>(gf + g);
                dr[r] = *reinterpret_cast<const float4*>(gd + g);
            }
        }

        #pragma unroll
        for (int jj = 0; jj < CHUNK; ++jj) {
            const float2 fd = ism[fb + jj];
            const float ft = fd.x;
            const float dd = fd.y;             // already dt*delta

            // off-critical-path combos
            const float cpd = cp  + dd;
            const float gdd = dtg + dd;
            const float cdd = cd  + dd;

            const float up   = (gam * ft) * mP;      // Vm = 1
            const float dtup = dt * up;

            // N1 = N(1-dd) + (dta*zoo + dte*P) + (dtg*Z + dtphi*D) + (8dd - dt*up)
            const float t1 = fmaf(dta, zoo, dte * P);
            const float t2 = fmaf(dtg, Z, dtphi * D);
            const float t3 = fmaf(8.0f, dd, -dtup);  // Q0 = 8
            const float t4 = fmaf(-dd, N, N);
            const float N1 = (t1 + t2) + (t3 + t4);

            // P1 = P(1 - cp - dd) + dt*up - dt*zoo
            const float q1 = fmaf(-cpd, P, P);
            const float q2 = fmaf(-dt, zoo, dtup);
            const float P1 = q1 + q2;

            // Z1 = Z(1 - dtg - dd) + dtb*zoo
            const float Z1 = fmaf(dtb, zoo, fmaf(-gdd, Z, Z));

            // D1 = D(1 - cd - dd) + dtr*P + dtab*zoo
            const float u1 = fmaf(-cdd, D, D);
            const float u2 = fmaf(dtr, P, dtab * zoo);
            const float D1 = u1 + u2;

            N = N1; P = P1; Z = Z1; D = D1;

            gam = N1 * rcp_approx(Kn + N1);
            mP  = fmaxf(thr, P1);
            const float RmZ = Rm * fmaxf(thr, Z1);
            const float ex  = ex2_approx(nl * mP);
            zoo = fmaf(-RmZ, ex, RmZ);
        }

        // exactly one output sample per 24-step chunk, compile-time position
        const int k = c + 1;
        op[k]      = N;
        op[8 + k]  = P;
        op[16 + k] = Z;
        op[24 + k] = D;

        __syncthreads();                       // all reads of ism done
    }
}

extern "C" void kernel_launch(void* const* d_in, const int* in_sizes, int n_in,
                              void* d_out, int out_size) {
    const float* X_in  = (const float*)d_in[0];
    const float* gf    = (const float*)d_in[1];
    const float* gd    = (const float*)d_in[2];
    const float* par   = (const float*)d_in[3];
    float* out = (float*)d_out;

    npzd_kernel<<<(BB * WW) / TPB, TPB>>>(X_in, gf, gd, par, out);
}

// round 7
// speedup vs baseline: 1.8111x; 1.1101x over previous
#include <cuda_runtime.h>

// NPZD Euler: 1024*52 independent 168-step chains.
// t_idx[w,j] = 168*w + j exactly -> f/delta are contiguous 168-float windows.
//
// Round-7 (best so far R6 = 35.2us, issue 41.9%):
//  * warp-autonomous blocks: TPB=32, grid=1664. All __syncthreads ->
//    __syncwarp (removes 14 block-wide barrier drains + inter-warp coupling;
//    balances 11-12 warps on every SM instead of 8-vs-12).
//  * bases[] SMEM replaced by __shfl_sync with dynamic source lane.
//  * dt folded into BOTH f and delta at STS time: SMEM holds (dt*f, dt*delta),
//    saving the dtup multiply each step.
//  * keeps: register-staged chunk prefetch (DRAM hidden under compute),
//    CHUNK=24 branchless sampling, pitch-25 float2 conflict-free SMEM,
//    tree-shaped update, raw ex2/rcp approx.

#define BB 1024
#define WW 52
#define HOURS 8760
#define TSTEPS 168
#define TPB 32
#define CHUNK 24
#define NCHUNK 7               // 7 * 24 = 168
#define PITCH 25               // float2 units; 50-word stride -> conflict-free

__device__ __forceinline__ float ex2_approx(float x) {
    float r;
    asm("ex2.approx.f32 %0, %1;" : "=f"(r) : "f"(x));
    return r;
}
__device__ __forceinline__ float rcp_approx(float x) {
    float r;
    asm("rcp.approx.f32 %0, %1;" : "=f"(r) : "f"(x));
    return r;
}

__global__ __launch_bounds__(TPB, 12) void npzd_kernel(
    const float* __restrict__ X_in,      // (B, W, 5, 1)
    const float* __restrict__ gf,        // (B, HOURS)
    const float* __restrict__ gd,        // (B, HOURS)
    const float* __restrict__ params,    // (B, 10)
    float* __restrict__ out)             // (B, W, 4, 8)
{
    __shared__ float2 ism[TPB * PITCH];  // interleaved (dt*f, dt*delta)

    const int t = threadIdx.x;           // lane
    const int p = blockIdx.x * TPB + t;  // pair index
    const int b = p / WW;
    const int w = p - b * WW;

    const int myBase = b * HOURS + w * TSTEPS;  // multiple of 8 -> f4-aligned

    const float dt  = 1.0f / 24.0f;
    const float thr = 0.01f;

    const float* pp = params + b * 10;
    const float Kn    = pp[0] * 1.0f;
    const float Rm    = pp[1] * 2.0f;
    const float gz    = pp[2] * 0.1f;
    const float lam   = pp[3] * 0.05f;
    const float eps   = pp[4] * 0.1f;
    const float alpha = pp[5] * 0.3f;
    const float beta  = pp[6] * 0.6f;
    const float rr    = pp[7] * 0.15f;
    const float phi   = pp[8] * 0.4f;
    const float Sw    = pp[9] * 0.1f;

    const float dta   = dt * alpha;
    const float dte   = dt * eps;
    const float dtg   = dt * gz;
    const float dtphi = dt * phi;
    const float dtb   = dt * beta;
    const float dtr   = dt * rr;
    const float dtab  = dt * (1.0f - alpha - beta);
    const float cp    = dt * (eps + rr);       // (eps + r)*dt
    const float cd    = dt * (phi + Sw);       // (phi + Sw)*dt
    const float nl    = -lam * 1.44269504f;    // fold log2(e) into lambda

    const float* xi = X_in + (size_t)p * 5;
    float N = xi[1];
    float P = xi[2];
    float Z = xi[3];
    float D = xi[4];

    float* op = out + (size_t)p * 32;          // [4 states][8 samples]
    op[0]  = N;
    op[8]  = P;
    op[16] = Z;
    op[24] = D;

    float gam = N * rcp_approx(Kn + N);
    float mP  = fmaxf(thr, P);
    float zoo;
    {
        float RmZ = Rm * fmaxf(thr, Z);
        float ex  = ex2_approx(nl * mP);
        zoo = fmaf(-RmZ, ex, RmZ);
    }

    const int fb = t * PITCH;

    // register staging for the next chunk (warp-cooperative slice, 48 floats)
    float4 fr[6], dr[6];

    // prefetch chunk 0: lane t covers float4 #e of row (bases via shfl)
    #pragma unroll
    for (int q = 0; q < 6; ++q) {
        int i   = q * TPB + t;               // 0 .. 191
        int row = i / 6;                     // 6 float4 per row
        int e   = i - row * 6;
        int g   = __shfl_sync(0xffffffffu, myBase, row) + e * 4;
        fr[q] = *reinterpret_cast<const float4*>(gf + g);
        dr[q] = *reinterpret_cast<const float4*>(gd + g);
    }

    #pragma unroll 1
    for (int c = 0; c < NCHUNK; ++c) {
        // STS staged registers -> SMEM, folding dt into both f and delta
        #pragma unroll
        for (int q = 0; q < 6; ++q) {
            int i   = q * TPB + t;
            int row = i / 6;
            int e   = i - row * 6;
            int so  = row * PITCH + e * 4;
            ism[so + 0] = make_float2(dt * fr[q].x, dt * dr[q].x);
            ism[so + 1] = make_float2(dt * fr[q].y, dt * dr[q].y);
            ism[so + 2] = make_float2(dt * fr[q].z, dt * dr[q].z);
            ism[so + 3] = make_float2(dt * fr[q].w, dt * dr[q].w);
        }
        __syncwarp();                        // chunk c visible warp-wide

        // prefetch chunk c+1 while computing chunk c (DRAM latency hidden)
        if (c < NCHUNK - 1) {
            const int cbase = (c + 1) * CHUNK;
            #pragma unroll
            for (int q = 0; q < 6; ++q) {
                int i   = q * TPB + t;
                int row = i / 6;
                int e   = i - row * 6;
                int g   = __shfl_sync(0xffffffffu, myBase, row) + cbase + e * 4;
                fr[q] = *reinterpret_cast<const float4*>(gf + g);
                dr[q] = *reinterpret_cast<const float4*>(gd + g);
            }
        }

        #pragma unroll
        for (int jj = 0; jj < CHUNK; ++jj) {
            const float2 fd = ism[fb + jj];
            const float fp = fd.x;           // dt*f
            const float dd = fd.y;           // dt*delta

            // off-critical-path combos
            const float cpd = cp  + dd;
            const float gdd = dtg + dd;
            const float cdd = cd  + dd;

            const float dtup = (gam * fp) * mP;      // Vm = 1, dt folded in fp

            // N1 = N(1-dd) + (dta*zoo + dte*P) + (dtg*Z + dtphi*D) + (8dd - dtup)
            const float t1 = fmaf(dta, zoo, dte * P);
            const float t2 = fmaf(dtg, Z, dtphi * D);
            const float t3 = fmaf(8.0f, dd, -dtup);  // Q0 = 8
            const float t4 = fmaf(-dd, N, N);
            const float N1 = (t1 + t2) + (t3 + t4);

            // P1 = P(1 - cp - dd) + dtup - dt*zoo
            const float q1 = fmaf(-cpd, P, P);
            const float q2 = fmaf(-dt, zoo, dtup);
            const float P1 = q1 + q2;

            // Z1 = Z(1 - dtg - dd) + dtb*zoo
            const float Z1 = fmaf(dtb, zoo, fmaf(-gdd, Z, Z));

            // D1 = D(1 - cd - dd) + dtr*P + dtab*zoo
            const float u1 = fmaf(-cdd, D, D);
            const float u2 = fmaf(dtr, P, dtab * zoo);
            const float D1 = u1 + u2;

            N = N1; P = P1; Z = Z1; D = D1;

            gam = N1 * rcp_approx(Kn + N1);
            mP  = fmaxf(thr, P1);
            const float RmZ = Rm * fmaxf(thr, Z1);
            const float ex  = ex2_approx(nl * mP);
            zoo = fmaf(-RmZ, ex, RmZ);
        }

        // exactly one output sample per 24-step chunk, compile-time position
        const int k = c + 1;
        op[k]      = N;
        op[8 + k]  = P;
        op[16 + k] = Z;
        op[24 + k] = D;

        __syncwarp();                        // all reads of ism done
    }
}

extern "C" void kernel_launch(void* const* d_in, const int* in_sizes, int n_in,
                              void* d_out, int out_size) {
    const float* X_in  = (const float*)d_in[0];
    const float* gf    = (const float*)d_in[1];
    const float* gd    = (const float*)d_in[2];
    const float* par   = (const float*)d_in[3];
    float* out = (float*)d_out;

    npzd_kernel<<<(BB * WW) / TPB, TPB>>>(X_in, gf, gd, par, out);
}

// round 8
// speedup vs baseline: 2.3438x; 1.2941x over previous
#include <cuda_runtime.h>

// NPZD Euler: 1024*52 independent 168-step chains.
// t_idx[w,j] = 168*w + j exactly -> f/delta are contiguous 168-float windows.
//
// Round-8 (best so far R7 = 31.7us, issue 48%, l1tex 58.3%):
//  * outputs staged in SMEM (pitch-33, conflict-free) and written once at
//    kernel end with fully coalesced warp-STGs: the old per-chunk op[] stores
//    had 128B lane stride -> 32 L1tex wavefronts per warp-STG, ~288 wavefront
//    cycles/warp of pure overhead + chunk-boundary serialization. Now ~32
//    total, off the hot path.
//  * keeps: warp-autonomous TPB=32 grid=1664, register-staged chunk prefetch,
//    CHUNK=24 branchless sampling, pitch-25 float2 conflict-free SMEM,
//    (dt*f, dt*delta) folding at STS time, tree-shaped update, raw ex2/rcp.

#define BB 1024
#define WW 52
#define HOURS 8760
#define TSTEPS 168
#define TPB 32
#define CHUNK 24
#define NCHUNK 7               // 7 * 24 = 168
#define PITCH 25               // float2 units; 50-word stride -> conflict-free
#define OPITCH 33              // output staging pitch: (t+j)%32 -> conflict-free

__device__ __forceinline__ float ex2_approx(float x) {
    float r;
    asm("ex2.approx.f32 %0, %1;" : "=f"(r) : "f"(x));
    return r;
}
__device__ __forceinline__ float rcp_approx(float x) {
    float r;
    asm("rcp.approx.f32 %0, %1;" : "=f"(r) : "f"(x));
    return r;
}

__global__ __launch_bounds__(TPB, 12) void npzd_kernel(
    const float* __restrict__ X_in,      // (B, W, 5, 1)
    const float* __restrict__ gf,        // (B, HOURS)
    const float* __restrict__ gd,        // (B, HOURS)
    const float* __restrict__ params,    // (B, 10)
    float* __restrict__ out)             // (B, W, 4, 8)
{
    __shared__ float2 ism[TPB * PITCH];  // interleaved (dt*f, dt*delta)
    __shared__ float  osm[TPB * OPITCH]; // per-lane output record staging

    const int t = threadIdx.x;           // lane
    const int p = blockIdx.x * TPB + t;  // pair index
    const int b = p / WW;
    const int w = p - b * WW;

    const int myBase = b * HOURS + w * TSTEPS;  // multiple of 8 -> f4-aligned

    const float dt  = 1.0f / 24.0f;
    const float thr = 0.01f;

    const float* pp = params + b * 10;
    const float Kn    = pp[0] * 1.0f;
    const float Rm    = pp[1] * 2.0f;
    const float gz    = pp[2] * 0.1f;
    const float lam   = pp[3] * 0.05f;
    const float eps   = pp[4] * 0.1f;
    const float alpha = pp[5] * 0.3f;
    const float beta  = pp[6] * 0.6f;
    const float rr    = pp[7] * 0.15f;
    const float phi   = pp[8] * 0.4f;
    const float Sw    = pp[9] * 0.1f;

    const float dta   = dt * alpha;
    const float dte   = dt * eps;
    const float dtg   = dt * gz;
    const float dtphi = dt * phi;
    const float dtb   = dt * beta;
    const float dtr   = dt * rr;
    const float dtab  = dt * (1.0f - alpha - beta);
    const float cp    = dt * (eps + rr);       // (eps + r)*dt
    const float cd    = dt * (phi + Sw);       // (phi + Sw)*dt
    const float nl    = -lam * 1.44269504f;    // fold log2(e) into lambda

    const float* xi = X_in + (size_t)p * 5;
    float N = xi[1];
    float P = xi[2];
    float Z = xi[3];
    float D = xi[4];

    // sample 0 into staging (record layout: [state*8 + k], k=0..7)
    const int ob = t * OPITCH;
    osm[ob + 0]  = N;
    osm[ob + 8]  = P;
    osm[ob + 16] = Z;
    osm[ob + 24] = D;

    float gam = N * rcp_approx(Kn + N);
    float mP  = fmaxf(thr, P);
    float zoo;
    {
        float RmZ = Rm * fmaxf(thr, Z);
        float ex  = ex2_approx(nl * mP);
        zoo = fmaf(-RmZ, ex, RmZ);
    }

    const int fb = t * PITCH;

    // register staging for the next chunk (warp-cooperative slice, 48 floats)
    float4 fr[6], dr[6];

    // prefetch chunk 0: lane t covers float4 #e of row (bases via shfl)
    #pragma unroll
    for (int q = 0; q < 6; ++q) {
        int i   = q * TPB + t;               // 0 .. 191
        int row = i / 6;                     // 6 float4 per row
        int e   = i - row * 6;
        int g   = __shfl_sync(0xffffffffu, myBase, row) + e * 4;
        fr[q] = *reinterpret_cast<const float4*>(gf + g);
        dr[q] = *reinterpret_cast<const float4*>(gd + g);
    }

    #pragma unroll 1
    for (int c = 0; c < NCHUNK; ++c) {
        // STS staged registers -> SMEM, folding dt into both f and delta
        #pragma unroll
        for (int q = 0; q < 6; ++q) {
            int i   = q * TPB + t;
            int row = i / 6;
            int e   = i - row * 6;
            int so  = row * PITCH + e * 4;
            ism[so + 0] = make_float2(dt * fr[q].x, dt * dr[q].x);
            ism[so + 1] = make_float2(dt * fr[q].y, dt * dr[q].y);
            ism[so + 2] = make_float2(dt * fr[q].z, dt * dr[q].z);
            ism[so + 3] = make_float2(dt * fr[q].w, dt * dr[q].w);
        }
        __syncwarp();                        // chunk c visible warp-wide

        // prefetch chunk c+1 while computing chunk c (DRAM latency hidden)
        if (c < NCHUNK - 1) {
            const int cbase = (c + 1) * CHUNK;
            #pragma unroll
            for (int q = 0; q < 6; ++q) {
                int i   = q * TPB + t;
                int row = i / 6;
                int e   = i - row * 6;
                int g   = __shfl_sync(0xffffffffu, myBase, row) + cbase + e * 4;
                fr[q] = *reinterpret_cast<const float4*>(gf + g);
                dr[q] = *reinterpret_cast<const float4*>(gd + g);
            }
        }

        #pragma unroll
        for (int jj = 0; jj < CHUNK; ++jj) {
            const float2 fd = ism[fb + jj];
            const float fp = fd.x;           // dt*f
            const float dd = fd.y;           // dt*delta

            // off-critical-path combos
            const float cpd = cp  + dd;
            const float gdd = dtg + dd;
            const float cdd = cd  + dd;

            const float dtup = (gam * fp) * mP;      // Vm = 1, dt folded in fp

            // N1 = N(1-dd) + (dta*zoo + dte*P) + (dtg*Z + dtphi*D) + (8dd - dtup)
            const float t1 = fmaf(dta, zoo, dte * P);
            const float t2 = fmaf(dtg, Z, dtphi * D);
            const float t3 = fmaf(8.0f, dd, -dtup);  // Q0 = 8
            const float t4 = fmaf(-dd, N, N);
            const float N1 = (t1 + t2) + (t3 + t4);

            // P1 = P(1 - cp - dd) + dtup - dt*zoo
            const float q1 = fmaf(-cpd, P, P);
            const float q2 = fmaf(-dt, zoo, dtup);
            const float P1 = q1 + q2;

            // Z1 = Z(1 - dtg - dd) + dtb*zoo
            const float Z1 = fmaf(dtb, zoo, fmaf(-gdd, Z, Z));

            // D1 = D(1 - cd - dd) + dtr*P + dtab*zoo
            const float u1 = fmaf(-cdd, D, D);
            const float u2 = fmaf(dtr, P, dtab * zoo);
            const float D1 = u1 + u2;

            N = N1; P = P1; Z = Z1; D = D1;

            gam = N1 * rcp_approx(Kn + N1);
            mP  = fmaxf(thr, P1);
            const float RmZ = Rm * fmaxf(thr, Z1);
            const float ex  = ex2_approx(nl * mP);
            zoo = fmaf(-RmZ, ex, RmZ);
        }

        // one output sample per 24-step chunk -> SMEM staging (conflict-free)
        const int k = c + 1;
        osm[ob + k]      = N;
        osm[ob + 8 + k]  = P;
        osm[ob + 16 + k] = Z;
        osm[ob + 24 + k] = D;

        __syncwarp();                        // all reads of ism done
    }

    // epilogue: coalesced output. Block owns out[blockIdx*1024 .. +1024).
    // linear o = s*32 + lane maps to record s (lane t'=s), element j=lane.
    __syncwarp();
    float* obase = out + (size_t)blockIdx.x * (TPB * 32);
    #pragma unroll
    for (int s = 0; s < 32; ++s) {
        obase[s * 32 + t] = osm[s * OPITCH + t];   // banks (s+t)%32: conflict-free
    }
}

extern "C" void kernel_launch(void* const* d_in, const int* in_sizes, int n_in,
                              void* d_out, int out_size) {
    const float* X_in  = (const float*)d_in[0];
    const float* gf    = (const float*)d_in[1];
    const float* gd    = (const float*)d_in[2];
    const float* par   = (const float*)d_in[3];
    float* out = (float*)d_out;

    npzd_kernel<<<(BB * WW) / TPB, TPB>>>(X_in, gf, gd, par, out);
}